// round 5
// baseline (speedup 1.0000x reference)
#include <cuda_runtime.h>

// Problem constants
constexpr int B = 256;
constexpr int T = 2048;
constexpr int D = 64;     // input dim
constexpr int H = 25;     // LSTM units
constexpr int G = 100;    // 4 gates * H
constexpr long long ROWS = (long long)B * T;   // 524288

// Scratch for layer-1 input projections: [B*T][25 units][4 gates] floats (~210 MB)
__device__ float g_xp[52428800];

// Packed fp32x2 FMA (2 fp32 MACs per issue, full precision)
__device__ __forceinline__ float2 ffma2(float2 a, float2 b, float2 c) {
    float2 d;
    asm("fma.rn.f32x2 %0, %1, %2, %3;"
        : "=l"(reinterpret_cast<unsigned long long &>(d))
        : "l"(reinterpret_cast<unsigned long long &>(a)),
          "l"(reinterpret_cast<unsigned long long &>(b)),
          "l"(reinterpret_cast<unsigned long long &>(c)));
    return d;
}

__device__ __forceinline__ float rcp_f(float x) {
    float r; asm("rcp.approx.f32 %0, %1;" : "=f"(r) : "f"(x)); return r;
}
// sigmoid via MUFU ex2 + MUFU rcp (no IEEE division): ~1e-7 abs error
__device__ __forceinline__ float sigm(float x)  { return rcp_f(1.0f + __expf(-x)); }
// tanh(x) = 2/(1+e^{-2x}) - 1 : ~2e-7 abs error
__device__ __forceinline__ float tanh_f(float x){ return fmaf(2.0f, rcp_f(1.0f + __expf(-2.0f * x)), -1.0f); }

// ---------------------------------------------------------------------------
// Kernel 1: layer-1 input projections.
// g_xp[row][u*4+g] = sum_j x[row][j] * Wx_g[j][u] + b_g[u]
// ---------------------------------------------------------------------------
constexpr int XROWS = 64;

__global__ __launch_bounds__(256) void xproj_kernel(
    const float* __restrict__ x,
    const float* __restrict__ Wxi, const float* __restrict__ bi,
    const float* __restrict__ Wxf, const float* __restrict__ bf,
    const float* __restrict__ Wxc, const float* __restrict__ bc,
    const float* __restrict__ Wxo, const float* __restrict__ bo)
{
    __shared__ float Ws[D * G];     // combined weights, [j][c] layout (c = g*25+u)
    __shared__ float xT[D][66];     // transposed x tile

    const int tid = threadIdx.x;
    const long long row0 = (long long)blockIdx.x * XROWS;

    for (int idx = tid; idx < D * G; idx += 256) {
        int j = idx / G, c = idx % G;
        int g = c / H, u = c % H;
        const float* W = (g == 0) ? Wxi : (g == 1) ? Wxf : (g == 2) ? Wxc : Wxo;
        Ws[idx] = W[j * H + u];
    }
    for (int idx = tid; idx < XROWS * 16; idx += 256) {
        int r = idx >> 4, jq = idx & 15;
        float4 v = *reinterpret_cast<const float4*>(&x[(row0 + r) * D + jq * 4]);
        xT[jq * 4 + 0][r] = v.x;
        xT[jq * 4 + 1][r] = v.y;
        xT[jq * 4 + 2][r] = v.z;
        xT[jq * 4 + 3][r] = v.w;
    }
    __syncthreads();

    if (tid < 200) {
        const int c  = tid % G;    // c = g*25+u
        const int rg = tid / G;    // row-half: 32 rows each
        const int g = c / H, u = c % H;
        const float bias = ((g == 0) ? bi : (g == 1) ? bf : (g == 2) ? bc : bo)[u];

        float2 acc[16];
        #pragma unroll
        for (int k = 0; k < 16; k++) acc[k] = make_float2(0.f, 0.f);

        #pragma unroll 2
        for (int j = 0; j < D; j++) {
            float w = Ws[j * G + c];
            float2 wp = make_float2(w, w);
            const float2* xr = reinterpret_cast<const float2*>(&xT[j][rg * 32]);
            #pragma unroll
            for (int k = 0; k < 16; k++) acc[k] = ffma2(xr[k], wp, acc[k]);
        }

        // output layout: [row][u*4 + g]
        float* outp = &g_xp[(row0 + rg * 32) * G + (u * 4 + g)];
        #pragma unroll
        for (int k = 0; k < 16; k++) {
            outp[(2 * k)     * G] = acc[k].x + bias;
            outp[(2 * k + 1) * G] = acc[k].y + bias;
        }
    }
}

// ---------------------------------------------------------------------------
// Kernel 2: warp-specialized fused recurrence.
// Block = 2 batch elements ("pairs"), 6 warps. Per pair:
//   warp A : L1 recurrence (h1_t) + output head (step t-3)
//   warp C : L2 input projection xg2_{t-1} = h1_{t-1} @ Wx2 + b2
//   warp B : L2 recurrence (h2_{t-2}) using C's preacts
// Single __syncthreads per step; double-buffered smem handoffs.
// Warp->SMSP mapping (wid%4) balanced: S0={A0,C0} S1={B0,C1} S2={A1} S3={B1}.
// ---------------------------------------------------------------------------
struct __align__(16) PairS {
    float h1[2][32];     // pads [25..31] stay 0
    float h2[2][32];
    float xp2[2][100];   // [buf][u*4+g] L2 gate preacts (incl. bias)
};

__global__ __launch_bounds__(192) void lstm_kernel(
    const float* __restrict__ Whi1, const float* __restrict__ Whf1,
    const float* __restrict__ Whc1, const float* __restrict__ Who1,
    const float* __restrict__ Wxi2, const float* __restrict__ Wxf2,
    const float* __restrict__ Wxc2, const float* __restrict__ Wxo2,
    const float* __restrict__ bi2,  const float* __restrict__ bf2,
    const float* __restrict__ bc2,  const float* __restrict__ bo2,
    const float* __restrict__ Whi2, const float* __restrict__ Whf2,
    const float* __restrict__ Whc2, const float* __restrict__ Who2,
    const float* __restrict__ Wout, const float* __restrict__ bout,
    float* __restrict__ out)
{
    __shared__ PairS sp[2];

    const int tid  = threadIdx.x;
    const int wid  = tid >> 5;
    const int lane = tid & 31;
    const int uu   = (lane < 25) ? lane : 24;   // clamped unit index (keeps loads in-bounds)

    // wid: 0->A p0, 1->B p0, 2->A p1, 3->B p1, 4->C p0, 5->C p1
    const int role = (wid < 4) ? (wid & 1) : 2;        // 0=A 1=B 2=C
    const int p    = (wid < 4) ? (wid >> 1) : (wid - 4);
    const long long bT = (long long)(blockIdx.x * 2 + p) * T;

    // Zero smem (hidden pads must be 0)
    {
        float* sz = reinterpret_cast<float*>(sp);
        for (int i = tid; i < (int)(2 * sizeof(PairS) / 4); i += 192) sz[i] = 0.f;
    }
    __syncthreads();

    if (role == 0) {
        // ---------------- Warp A: L1 recurrence + output head ----------------
        float2 wi[13], wf[13], wc[13], wo4[13];
        #pragma unroll
        for (int jp = 0; jp < 13; jp++) {
            int j0 = 2 * jp, j1 = 2 * jp + 1;
            wi[jp].x  = Whi1[j0 * 25 + uu];  wi[jp].y  = (j1 < 25) ? Whi1[j1 * 25 + uu] : 0.f;
            wf[jp].x  = Whf1[j0 * 25 + uu];  wf[jp].y  = (j1 < 25) ? Whf1[j1 * 25 + uu] : 0.f;
            wc[jp].x  = Whc1[j0 * 25 + uu];  wc[jp].y  = (j1 < 25) ? Whc1[j1 * 25 + uu] : 0.f;
            wo4[jp].x = Who1[j0 * 25 + uu];  wo4[jp].y = (j1 < 25) ? Who1[j1 * 25 + uu] : 0.f;
        }
        const float wout_u = (lane < 25) ? Wout[lane] : 0.f;
        const float bo = bout[0];
        float c1 = 0.f;

        float4 q[4];
        #pragma unroll
        for (int k = 0; k < 4; k++)
            q[k] = *reinterpret_cast<const float4*>(&g_xp[(bT + k) * G + uu * 4]);

        for (int tb = 0; tb < T + 4; tb += 4) {
            #pragma unroll
            for (int k = 0; k < 4; k++) {
                const int t = tb + k;
                __syncthreads();

                if (t < T) {
                    float4 xg = q[k];
                    if (t + 4 < T)
                        q[k] = *reinterpret_cast<const float4*>(&g_xp[(bT + t + 4) * G + uu * 4]);
                    const float2* hp = reinterpret_cast<const float2*>(sp[p].h1[(t + 1) & 1]);
                    float2 ai = make_float2(0.f, 0.f), af = ai, ac = ai, ao = ai;
                    #pragma unroll
                    for (int jp = 0; jp < 13; jp++) {
                        float2 h = hp[jp];
                        ai = ffma2(h, wi[jp],  ai);
                        af = ffma2(h, wf[jp],  af);
                        ac = ffma2(h, wc[jp],  ac);
                        ao = ffma2(h, wo4[jp], ao);
                    }
                    float gi = sigm  (ai.x + ai.y + xg.x);
                    float gf = sigm  (af.x + af.y + xg.y);
                    float gg = tanh_f(ac.x + ac.y + xg.z);
                    float go = sigm  (ao.x + ao.y + xg.w);
                    c1 = fmaf(gf, c1, gi * gg);
                    float h1v = go * tanh_f(c1);
                    if (lane < 25) sp[p].h1[t & 1][lane] = h1v;
                }

                if (t >= 3 && t <= T + 2) {    // output head, s = t-3
                    const int s = t - 3;
                    float term = sp[p].h2[(t + 1) & 1][lane] * wout_u;
                    #pragma unroll
                    for (int m = 16; m > 0; m >>= 1)
                        term += __shfl_xor_sync(0xffffffffu, term, m);
                    if (lane == 0) out[bT + s] = sigm(term + bo);
                }
            }
        }
    } else if (role == 1) {
        // ---------------- Warp B: L2 recurrence ----------------
        float2 vi[13], vf[13], vc[13], vo[13];
        #pragma unroll
        for (int jp = 0; jp < 13; jp++) {
            int j0 = 2 * jp, j1 = 2 * jp + 1;
            vi[jp].x = Whi2[j0 * 25 + uu];  vi[jp].y = (j1 < 25) ? Whi2[j1 * 25 + uu] : 0.f;
            vf[jp].x = Whf2[j0 * 25 + uu];  vf[jp].y = (j1 < 25) ? Whf2[j1 * 25 + uu] : 0.f;
            vc[jp].x = Whc2[j0 * 25 + uu];  vc[jp].y = (j1 < 25) ? Whc2[j1 * 25 + uu] : 0.f;
            vo[jp].x = Who2[j0 * 25 + uu];  vo[jp].y = (j1 < 25) ? Who2[j1 * 25 + uu] : 0.f;
        }
        float c2 = 0.f;

        #pragma unroll 2
        for (int t = 0; t < T + 4; t++) {
            __syncthreads();
            if (t >= 2 && t <= T + 1) {
                const int s = t - 2;
                float4 xp = *reinterpret_cast<const float4*>(&sp[p].xp2[s & 1][uu * 4]);
                const float2* hp = reinterpret_cast<const float2*>(sp[p].h2[(s + 1) & 1]);
                float2 ai = make_float2(0.f, 0.f), af = ai, ac = ai, ao = ai;
                #pragma unroll
                for (int jp = 0; jp < 13; jp++) {
                    float2 h = hp[jp];
                    ai = ffma2(h, vi[jp], ai);
                    af = ffma2(h, vf[jp], af);
                    ac = ffma2(h, vc[jp], ac);
                    ao = ffma2(h, vo[jp], ao);
                }
                float gi = sigm  (ai.x + ai.y + xp.x);
                float gf = sigm  (af.x + af.y + xp.y);
                float gg = tanh_f(ac.x + ac.y + xp.z);
                float go = sigm  (ao.x + ao.y + xp.w);
                c2 = fmaf(gf, c2, gi * gg);
                float h2v = go * tanh_f(c2);
                if (lane < 25) sp[p].h2[s & 1][lane] = h2v;
            }
        }
    } else {
        // ---------------- Warp C: L2 input projection ----------------
        float2 xi[13], xf[13], xc[13], xo[13];
        #pragma unroll
        for (int jp = 0; jp < 13; jp++) {
            int j0 = 2 * jp, j1 = 2 * jp + 1;
            xi[jp].x = Wxi2[j0 * 25 + uu];  xi[jp].y = (j1 < 25) ? Wxi2[j1 * 25 + uu] : 0.f;
            xf[jp].x = Wxf2[j0 * 25 + uu];  xf[jp].y = (j1 < 25) ? Wxf2[j1 * 25 + uu] : 0.f;
            xc[jp].x = Wxc2[j0 * 25 + uu];  xc[jp].y = (j1 < 25) ? Wxc2[j1 * 25 + uu] : 0.f;
            xo[jp].x = Wxo2[j0 * 25 + uu];  xo[jp].y = (j1 < 25) ? Wxo2[j1 * 25 + uu] : 0.f;
        }
        const float bbi = bi2[uu], bbf = bf2[uu], bbc = bc2[uu], bbo = bo2[uu];

        #pragma unroll 2
        for (int t = 0; t < T + 4; t++) {
            __syncthreads();
            if (t >= 1 && t <= T) {
                const int s = t - 1;
                const float2* hp = reinterpret_cast<const float2*>(sp[p].h1[s & 1]);
                float2 ai = make_float2(0.f, 0.f), af = ai, ac = ai, ao = ai;
                #pragma unroll
                for (int jp = 0; jp < 13; jp++) {
                    float2 h = hp[jp];
                    ai = ffma2(h, xi[jp], ai);
                    af = ffma2(h, xf[jp], af);
                    ac = ffma2(h, xc[jp], ac);
                    ao = ffma2(h, xo[jp], ao);
                }
                if (lane < 25)
                    *reinterpret_cast<float4*>(&sp[p].xp2[s & 1][lane * 4]) =
                        make_float4(ai.x + ai.y + bbi, af.x + af.y + bbf,
                                    ac.x + ac.y + bbc, ao.x + ao.y + bbo);
            }
        }
    }
}

// ---------------------------------------------------------------------------
// Host launcher. Input order detected from in_sizes (same logic as R3, passed):
//   dict order      : x, Wout(25), bout(1), l1_*(12), l2_*(12)
//   signature order : x, l1_*(12), l2_*(12), Wout, bout
// Per-layer order: Wxi, bi, Whi, Wxf, bf, Whf, Wxc, bc, Whc, Wxo, bo, Who
// ---------------------------------------------------------------------------
extern "C" void kernel_launch(void* const* d_in, const int* in_sizes, int n_in,
                              void* d_out, int out_size) {
    const float* p[27];
    for (int i = 0; i < 27 && i < n_in; i++) p[i] = (const float*)d_in[i];
    const float* x = p[0];

    int l1, l2, iWout, ibout;
    if (n_in >= 3 && in_sizes[1] == H) {   // dict order (Wout right after x)
        iWout = 1; ibout = 2; l1 = 3; l2 = 15;
    } else {                                // reference-signature order
        l1 = 1; l2 = 13; iWout = 25; ibout = 26;
    }

    xproj_kernel<<<(int)(ROWS / XROWS), 256>>>(
        x,
        p[l1 + 0], p[l1 + 1],    // Wxi, bi
        p[l1 + 3], p[l1 + 4],    // Wxf, bf
        p[l1 + 6], p[l1 + 7],    // Wxc, bc
        p[l1 + 9], p[l1 + 10]);  // Wxo, bo

    lstm_kernel<<<B / 2, 192>>>(
        p[l1 + 2], p[l1 + 5], p[l1 + 8], p[l1 + 11],     // l1 Whi, Whf, Whc, Who
        p[l2 + 0], p[l2 + 3], p[l2 + 6], p[l2 + 9],      // l2 Wxi, Wxf, Wxc, Wxo
        p[l2 + 1], p[l2 + 4], p[l2 + 7], p[l2 + 10],     // l2 bi, bf, bc, bo
        p[l2 + 2], p[l2 + 5], p[l2 + 8], p[l2 + 11],     // l2 Whi, Whf, Whc, Who
        p[iWout], p[ibout],
        (float*)d_out);
}